// round 1
// baseline (speedup 1.0000x reference)
#include <cuda_runtime.h>

#define NATOM 24
#define NSP 4
#define NPAIR 10
#define RADW 64          // NSP * 16
#define ANGW 320         // NPAIR * 32
#define OUTW 384
#define NJK 276          // C(24,2)
#define THREADS 256

// cos/sin of SHF_Z[t] = (t+0.5)*pi/8, t=0..7
__constant__ float COSZ[8] = {
     0.980785280403230449f,  0.831469612302545237f,  0.555570233019602225f,  0.195090322016128268f,
    -0.195090322016128268f, -0.555570233019602225f, -0.831469612302545237f, -0.980785280403230449f };
__constant__ float SINZ[8] = {
     0.195090322016128268f,  0.555570233019602225f,  0.831469612302545237f,  0.980785280403230449f,
     0.980785280403230449f,  0.831469612302545237f,  0.555570233019602225f,  0.195090322016128268f };

__global__ __launch_bounds__(THREADS)
void aev_kernel(const int* __restrict__ g_species,
                const float* __restrict__ g_coords,
                float* __restrict__ g_out, int M)
{
    const int m = blockIdx.x;
    if (m >= M) return;

    __shared__ float sc[NATOM][3];
    __shared__ int   ssp[NATOM];
    __shared__ float sdist[NATOM][NATOM];
    __shared__ float sfca[NATOM][NATOM];
    __shared__ float sfcr[NATOM][NATOM];
    __shared__ float acc[NATOM][OUTW];

    const int tid = threadIdx.x;

    if (tid < NATOM) {
        ssp[tid] = g_species[m * NATOM + tid];
        sc[tid][0] = g_coords[(m * NATOM + tid) * 3 + 0];
        sc[tid][1] = g_coords[(m * NATOM + tid) * 3 + 1];
        sc[tid][2] = g_coords[(m * NATOM + tid) * 3 + 2];
    }
    for (int idx = tid; idx < NATOM * OUTW; idx += THREADS)
        ((float*)acc)[idx] = 0.0f;
    __syncthreads();

    // ---- phase 1: pairwise tables -------------------------------------
    for (int p = tid; p < NATOM * NATOM; p += THREADS) {
        int i = p / NATOM, j = p % NATOM;
        float dx = sc[j][0] - sc[i][0];
        float dy = sc[j][1] - sc[i][1];
        float dz = sc[j][2] - sc[i][2];
        float d2 = dx * dx + dy * dy + dz * dz;
        float d = (i == j) ? 1.0f : sqrtf(d2);
        sdist[i][j] = d;
        bool ok = (i != j);
        float fca = (ok && d <= 3.5f) ? (0.5f * __cosf(0.897597901025655210f * d) + 0.5f) : 0.0f;
        float fcr = (ok && d <= 5.2f) ? (0.5f * __cosf(0.604152493782718100f * d) + 0.5f) : 0.0f;
        sfca[i][j] = fca;
        sfcr[i][j] = fcr;
    }
    __syncthreads();

    // ---- phase 2: radial ----------------------------------------------
    for (int p = tid; p < NATOM * NATOM; p += THREADS) {
        int i = p / NATOM, j = p % NATOM;
        float fcr = sfcr[i][j];
        if (fcr > 0.0f) {
            float d = sdist[i][j];
            float* dst = &acc[i][ssp[j] * 16];
            float q = 0.25f * fcr;
            #pragma unroll
            for (int r = 0; r < 16; r++) {
                float u = d - (0.9f + 0.26875f * (float)r);
                atomicAdd(&dst[r], q * __expf(-16.0f * u * u));
            }
        }
    }

    // ---- phase 3: angular (triples i, j<k) ----------------------------
    // No sync needed between phase 2 and 3: both only read phase-1 data
    // (synced above) and write disjoint acc columns via atomics.
    for (int t = tid; t < NATOM * NJK; t += THREADS) {
        int i = t / NJK;
        int pq = t % NJK;
        int j = 0, rem = pq;
        while (rem >= (NATOM - 1 - j)) { rem -= (NATOM - 1 - j); j++; }
        int k = j + 1 + rem;

        float w = sfca[i][j] * sfca[i][k];
        if (w > 0.0f) {
            float dij = sdist[i][j], dik = sdist[i][k];
            float ax = sc[j][0] - sc[i][0];
            float ay = sc[j][1] - sc[i][1];
            float az = sc[j][2] - sc[i][2];
            float bx = sc[k][0] - sc[i][0];
            float by = sc[k][1] - sc[i][1];
            float bz = sc[k][2] - sc[i][2];
            float dot = ax * bx + ay * by + az * bz;
            float c = 0.95f * dot / (dij * dik);
            float s = sqrtf(fmaxf(0.0f, 1.0f - c * c));
            float davg = 0.5f * (dij + dik);

            int sj = ssp[j], sk = ssp[k];
            int lo = min(sj, sk), hi = max(sj, sk);
            int pidx = lo * NSP - (lo * (lo - 1)) / 2 + (hi - lo);
            float* dst = &acc[i][RADW + pidx * 32];

            float f2[4];
            #pragma unroll
            for (int a = 0; a < 4; a++) {
                float u = davg - (0.9f + 0.65f * (float)a);
                f2[a] = __expf(-8.0f * u * u);
            }
            float w2 = 2.0f * w;
            #pragma unroll
            for (int z = 0; z < 8; z++) {
                float cz = 0.5f * (1.0f + c * COSZ[z] + s * SINZ[z]);
                float x = cz * cz;   // ^2
                x = x * x;           // ^4
                x = x * x;           // ^8
                x = x * x;           // ^16
                x = x * x;           // ^32
                float t1 = w2 * x;
                #pragma unroll
                for (int a = 0; a < 4; a++)
                    atomicAdd(&dst[a * 8 + z], t1 * f2[a]);
            }
        }
    }
    __syncthreads();

    // ---- phase 4: writeout --------------------------------------------
    const float* src = (const float*)acc;
    float* dstg = g_out + (size_t)m * NATOM * OUTW;
    for (int idx = tid; idx < NATOM * OUTW; idx += THREADS)
        dstg[idx] = src[idx];
}

extern "C" void kernel_launch(void* const* d_in, const int* in_sizes, int n_in,
                              void* d_out, int out_size)
{
    const int*   species = (const int*)d_in[0];
    const float* coords  = (const float*)d_in[1];
    // d_in[2] (coefficients) unused by the reference output
    int M = in_sizes[0] / NATOM;
    aev_kernel<<<M, THREADS>>>(species, coords, (float*)d_out, M);
}

// round 3
// speedup vs baseline: 5.2105x; 5.2105x over previous
#include <cuda_runtime.h>

#define NATOM 24
#define NSP 4
#define OUTW 384          // 64 radial + 320 angular
#define RADW 64
#define NJK 276           // C(24,2)
#define CPB 6             // centers per block
#define PARTS 4           // blocks per molecule
#define THREADS 256
#define NTRI (CPB * NJK)  // 1656 triples per block

// cos/sin of SHF_Z[t] = (t+0.5)*pi/8
__constant__ float COSZ[8] = {
     0.980785280403230449f,  0.831469612302545237f,  0.555570233019602225f,  0.195090322016128268f,
    -0.195090322016128268f, -0.555570233019602225f, -0.831469612302545237f, -0.980785280403230449f };
__constant__ float SINZ[8] = {
     0.195090322016128268f,  0.555570233019602225f,  0.831469612302545237f,  0.980785280403230449f,
     0.980785280403230449f,  0.831469612302545237f,  0.555570233019602225f,  0.195090322016128268f };

__global__ __launch_bounds__(THREADS)
void aev_kernel(const int* __restrict__ g_species,
                const float* __restrict__ g_coords,
                float* __restrict__ g_out, int M)
{
    const int bid  = blockIdx.x;
    const int m    = bid >> 2;           // molecule
    const int part = bid & 3;            // which 6-center slice
    const int ibase = part * CPB;
    if (m >= M) return;

    __shared__ float sc[NATOM][3];
    __shared__ int   ssp[NATOM];
    __shared__ unsigned char sj[NJK], sk[NJK];
    __shared__ float sdist[CPB][NATOM];
    __shared__ float sfca [CPB][NATOM];
    __shared__ float sfcr [CPB][NATOM];
    __shared__ float acc[CPB * OUTW];    // 9216 B

    const int tid  = threadIdx.x;
    const int lane = tid & 31;
    const int warp = tid >> 5;

    // ---- init ---------------------------------------------------------
    if (tid < NATOM) {
        ssp[tid]  = g_species[m * NATOM + tid];
        sc[tid][0] = g_coords[(m * NATOM + tid) * 3 + 0];
        sc[tid][1] = g_coords[(m * NATOM + tid) * 3 + 1];
        sc[tid][2] = g_coords[(m * NATOM + tid) * 3 + 2];
    }
    // FIX (R2 bug): NJK=276 > THREADS=256, must stride.
    for (int idx = tid; idx < NJK; idx += THREADS) {
        int j = 0, rem = idx;
        while (rem >= NATOM - 1 - j) { rem -= NATOM - 1 - j; j++; }
        sj[idx] = (unsigned char)j;
        sk[idx] = (unsigned char)(j + 1 + rem);
    }
    for (int idx = tid; idx < CPB * OUTW; idx += THREADS) acc[idx] = 0.0f;
    __syncthreads();

    // ---- phase 1: pair tables for our 6 centers ------------------------
    if (tid < CPB * NATOM) {
        int il = tid / NATOM, j = tid % NATOM;
        int ig = ibase + il;
        float dx = sc[j][0] - sc[ig][0];
        float dy = sc[j][1] - sc[ig][1];
        float dz = sc[j][2] - sc[ig][2];
        float d2 = dx * dx + dy * dy + dz * dz;
        float d  = (ig == j) ? 1.0f : sqrtf(d2);
        bool ok = (ig != j);
        sdist[il][j] = d;
        sfca[il][j] = (ok && d <= 3.5f) ? (0.5f * __cosf(0.897597901025655210f * d) + 0.5f) : 0.0f;
        sfcr[il][j] = (ok && d <= 5.2f) ? (0.5f * __cosf(0.604152493782718100f * d) + 0.5f) : 0.0f;
    }
    __syncthreads();

    // ---- phase 2: radial (per-thread, 144 pairs) -----------------------
    if (tid < CPB * NATOM) {
        int il = tid / NATOM, j = tid % NATOM;
        float fcr = sfcr[il][j];
        if (fcr > 0.0f) {
            float d = sdist[il][j];
            float* dst = &acc[il * OUTW + ssp[j] * 16];
            float q = 0.25f * fcr;
            #pragma unroll
            for (int r = 0; r < 16; r++) {
                float u = d - (0.9f + 0.26875f * (float)r);
                atomicAdd(&dst[r], q * __expf(-16.0f * u * u));
            }
        }
    }

    // ---- phase 3: angular, warp-cooperative ----------------------------
    // Each lane screens one triple; live triples are broadcast and all 32
    // lanes each compute one of the 32 (a,z) output elements -> one atomic
    // to 32 consecutive floats (bank-conflict-free).
    const int a_l = lane >> 3;          // 0..3  (SHF_A index)
    const int z_l = lane & 7;           // 0..7  (SHF_Z index)
    const float cz_c = COSZ[z_l], sz_c = SINZ[z_l];
    const float shfa = 0.9f + 0.65f * (float)a_l;

    for (int base = warp * 32; base < NTRI; base += THREADS) {
        int t = base + lane;
        bool live = false;
        float c = 0.f, s = 0.f, davg = 0.f, w2 = 0.f;
        int doff = 0;
        if (t < NTRI) {
            int il = t / NJK;
            int pq = t - il * NJK;
            int j = sj[pq], k = sk[pq];
            float w = sfca[il][j] * sfca[il][k];
            if (w > 0.0f) {
                int ig = ibase + il;
                float dij = sdist[il][j], dik = sdist[il][k];
                float ax = sc[j][0] - sc[ig][0];
                float ay = sc[j][1] - sc[ig][1];
                float az = sc[j][2] - sc[ig][2];
                float bx = sc[k][0] - sc[ig][0];
                float by = sc[k][1] - sc[ig][1];
                float bz = sc[k][2] - sc[ig][2];
                float dot = ax * bx + ay * by + az * bz;
                c = 0.95f * dot / (dij * dik);
                s = sqrtf(fmaxf(0.0f, 1.0f - c * c));
                davg = 0.5f * (dij + dik);
                w2 = 2.0f * w;
                int sjj = ssp[j], skk = ssp[k];
                int lo = min(sjj, skk), hi = max(sjj, skk);
                int pidx = lo * NSP - (lo * (lo - 1)) / 2 + (hi - lo);
                doff = il * OUTW + RADW + pidx * 32;
                live = true;
            }
        }
        unsigned mask = __ballot_sync(0xffffffffu, live);
        while (mask) {
            int src = __ffs(mask) - 1;
            mask &= mask - 1;
            float cc = __shfl_sync(0xffffffffu, c,    src);
            float ss = __shfl_sync(0xffffffffu, s,    src);
            float dv = __shfl_sync(0xffffffffu, davg, src);
            float ww = __shfl_sync(0xffffffffu, w2,   src);
            int   od = __shfl_sync(0xffffffffu, doff, src);
            float cz = 0.5f * (1.0f + cc * cz_c + ss * sz_c);
            float x = cz * cz;  // ^2
            x = x * x;          // ^4
            x = x * x;          // ^8
            x = x * x;          // ^16
            x = x * x;          // ^32
            float u = dv - shfa;
            float val = ww * x * __expf(-8.0f * u * u);
            atomicAdd(&acc[od + a_l * 8 + z_l], val);
        }
    }
    __syncthreads();

    // ---- phase 4: writeout --------------------------------------------
    float* dstg = g_out + (size_t)m * NATOM * OUTW + (size_t)ibase * OUTW;
    for (int idx = tid; idx < CPB * OUTW; idx += THREADS)
        dstg[idx] = acc[idx];
}

extern "C" void kernel_launch(void* const* d_in, const int* in_sizes, int n_in,
                              void* d_out, int out_size)
{
    const int*   species = (const int*)d_in[0];
    const float* coords  = (const float*)d_in[1];
    int M = in_sizes[0] / NATOM;
    aev_kernel<<<M * PARTS, THREADS>>>(species, coords, (float*)d_out, M);
}